// round 6
// baseline (speedup 1.0000x reference)
#include <cuda_runtime.h>
#include <cuda_fp16.h>
#include <cstdint>

// ---------------- problem constants ----------------
#define BATCH   16
#define C_IN    64
#define C_OUT   128
#define HH      128
#define WW      128
#define NTAP    9

// ---- 2D output tile: 8 rows x 16 cols = 128 pixels (M) ----
#define TR      8
#define TC      16
#define AH      10               // window rows  (TR + 2)
#define AW      18               // window cols  (TC + 2)
#define A_ROWS  (AH * AW)        // 180 pixel-rows in A

// ---- smem layout (dynamic) ----
#define ROWB     144
#define A_BYTES  (A_ROWS * ROWB)             // 25920
#define B_TILE   (128 * ROWB)                // 18432
#define NSTAGE   4
#define SMEM_B0  A_BYTES
#define SMEM_MAIN (A_BYTES + NSTAGE * B_TILE)   // 99648

// ---------------- device globals (scratch) ----------------
__device__ __half g_wt[NTAP * C_OUT * C_IN];              // [tap][oc][ic]

// ---------------- ptx helpers ----------------
__device__ __forceinline__ uint32_t smem_u32(const void* p) {
    uint32_t a;
    asm("{ .reg .u64 t; cvta.to.shared.u64 t, %1; cvt.u32.u64 %0, t; }" : "=r"(a) : "l"(p));
    return a;
}
__device__ __forceinline__ void cp_async16(uint32_t dst, const void* src) {
    asm volatile("cp.async.cg.shared.global [%0], [%1], 16;" :: "r"(dst), "l"(src));
}
__device__ __forceinline__ void cp_commit() {
    asm volatile("cp.async.commit_group;" ::: "memory");
}
template <int N>
__device__ __forceinline__ void cp_wait() {
    asm volatile("cp.async.wait_group %0;" :: "n"(N) : "memory");
}
__device__ __forceinline__ void ldm_x4(uint32_t& r0, uint32_t& r1, uint32_t& r2, uint32_t& r3, uint32_t addr) {
    asm volatile("ldmatrix.sync.aligned.m8n8.x4.shared.b16 {%0,%1,%2,%3}, [%4];"
                 : "=r"(r0), "=r"(r1), "=r"(r2), "=r"(r3) : "r"(addr));
}
__device__ __forceinline__ void mma16816(float* c, uint32_t a0, uint32_t a1, uint32_t a2, uint32_t a3,
                                         uint32_t b0, uint32_t b1) {
    asm volatile("mma.sync.aligned.m16n8k16.row.col.f32.f16.f16.f32 "
                 "{%0,%1,%2,%3}, {%4,%5,%6,%7}, {%8,%9}, {%0,%1,%2,%3};"
                 : "+f"(c[0]), "+f"(c[1]), "+f"(c[2]), "+f"(c[3])
                 : "r"(a0), "r"(a1), "r"(a2), "r"(a3), "r"(b0), "r"(b1));
}

// ---------------- prep: weights fp32 -> fp16 [tap][oc][ic] ----------------
__global__ void prep_weights(const float* __restrict__ w) {
    int idx = blockIdx.x * 256 + threadIdx.x;
    if (idx >= NTAP * C_OUT * C_IN) return;
    int ic  = idx & 63;
    int oc  = (idx >> 6) & 127;
    int tap = idx >> 13;
    int i = oc >> 3, p = oc & 7;
    int j = ic >> 3, q = ic & 7;
    int kh = tap / 3, kw = tap % 3;
    g_wt[idx] = __float2half_rn(w[i * 4608 + j * 576 + p * 72 + q * 9 + kh * 3 + kw]);
}

// ---------------- B-tap loader (cp.async, one commit group) ----------------
__device__ __forceinline__ void load_B(uint32_t sB, int tap, int tid) {
    const __half* bsrc = g_wt + (size_t)tap * C_OUT * C_IN;
    #pragma unroll
    for (int i = 0; i < 4; ++i) {
        int idx = tid + i * 256;
        int oc = idx >> 3, c = idx & 7;
        cp_async16(sB + oc * ROWB + c * 16, bsrc + (size_t)oc * C_IN + c * 8);
    }
    cp_commit();
}

// ---------------- main kernel ----------------
__global__ __launch_bounds__(256, 2)
void oct_mma_kernel(const float* __restrict__ x,
                    const float* __restrict__ bias,
                    float* __restrict__ out) {
    extern __shared__ char smem[];
    __shared__ float bias_s[C_OUT];
    const uint32_t sb = smem_u32(smem);
    const int tid  = threadIdx.x;
    const int wid  = tid >> 5;
    const int lane = tid & 31;
    const int mwarp = wid & 3;        // m block of 32 (= 2 tile rows)
    const int nwarp = wid >> 2;       // n block of 64

    const int tc = blockIdx.x & 7;    // tile col (16 px)
    const int tr = blockIdx.x >> 3;   // tile row (8 px)
    const int b  = blockIdx.y;        // batch

    if (tid < C_OUT) bias_s[tid] = bias[tid];

    // ---- start B ring early (taps 0..2) ----
    load_B(sb + SMEM_B0 + 0 * B_TILE, 0, tid);
    load_B(sb + SMEM_B0 + 1 * B_TILE, 1, tid);
    load_B(sb + SMEM_B0 + 2 * B_TILE, 2, tid);

    // ---- fused transpose: x NCHW fp32 -> A smem [pixel][ic] fp16 ----
    {
        const float* xb = x + (size_t)b * C_IN * HH * WW;
        const int R0 = tr * TR;       // padded-space window origin
        const int C0 = tc * TC;
        #pragma unroll 5
        for (int idx = tid; idx < C_IN * AH * AW; idx += 256) {
            int c  = idx % AW;
            int t2 = idx / AW;
            int r  = t2 % AH;
            int ic = t2 / AH;
            int R = R0 + r, C = C0 + c;
            float v = 0.0f;
            if (R >= 1 && R <= HH && C >= 1 && C <= WW)
                v = xb[((size_t)ic * HH + (R - 1)) * WW + (C - 1)];
            *(__half*)(smem + (r * AW + c) * ROWB + ic * 2) = __float2half_rn(v);
        }
    }

    float acc[2][8][4];
    #pragma unroll
    for (int mf = 0; mf < 2; ++mf)
        #pragma unroll
        for (int nf = 0; nf < 8; ++nf)
            #pragma unroll
            for (int c = 0; c < 4; ++c) acc[mf][nf][c] = 0.0f;

    // lane-constant ldmatrix offsets
    // A fragment: 16 M-rows = 16 pixels of one tile row; lane row index = pixel col c
    const int a_row_local = ((lane >> 3) & 1) * 8 + (lane & 7);    // 0..15 = pixel col
    const uint32_t a_off = (uint32_t)((mwarp * 2) * AW + a_row_local) * ROWB + (lane >> 4) * 16;
    const int b_row = ((lane >> 4) << 3) + (lane & 7);
    const uint32_t b_off = (uint32_t)(nwarp * 64 + b_row) * ROWB + ((lane >> 3) & 1) * 16;

    const int shifts[NTAP] = {0, 1, 2, AW, AW + 1, AW + 2, 2 * AW, 2 * AW + 1, 2 * AW + 2};

    #pragma unroll
    for (int t = 0; t < NTAP; ++t) {
        if (t < NTAP - 2)      cp_wait<2>();
        else if (t == NTAP - 2) cp_wait<1>();
        else                    cp_wait<0>();
        __syncthreads();
        if (t + 3 < NTAP)
            load_B(sb + SMEM_B0 + (uint32_t)((t + 3) % NSTAGE) * B_TILE, t + 3, tid);

        const uint32_t aB = sb + a_off + (uint32_t)shifts[t] * ROWB;
        const uint32_t bB = sb + SMEM_B0 + (uint32_t)(t % NSTAGE) * B_TILE + b_off;
        #pragma unroll
        for (int ks = 0; ks < 4; ++ks) {
            uint32_t a0[4], a1[4];
            ldm_x4(a0[0], a0[1], a0[2], a0[3], aB + ks * 32);
            ldm_x4(a1[0], a1[1], a1[2], a1[3], aB + AW * ROWB + ks * 32);   // mf=1: next tile row
            #pragma unroll
            for (int nf2 = 0; nf2 < 4; ++nf2) {
                uint32_t bb[4];
                ldm_x4(bb[0], bb[1], bb[2], bb[3], bB + nf2 * 16 * ROWB + ks * 32);
                mma16816(acc[0][nf2 * 2 + 0], a0[0], a0[1], a0[2], a0[3], bb[0], bb[1]);
                mma16816(acc[0][nf2 * 2 + 1], a0[0], a0[1], a0[2], a0[3], bb[2], bb[3]);
                mma16816(acc[1][nf2 * 2 + 0], a1[0], a1[1], a1[2], a1[3], bb[0], bb[1]);
                mma16816(acc[1][nf2 * 2 + 1], a1[0], a1[1], a1[2], a1[3], bb[2], bb[3]);
            }
        }
    }
    __syncthreads();   // protect smem reuse by epilogue

    // ---- epilogue: transpose (bias folded) through smem -> coalesced stores ----
    float* so = (float*)smem;   // [oc][136]
    #pragma unroll
    for (int mf = 0; mf < 2; ++mf)
        #pragma unroll
        for (int nf = 0; nf < 8; ++nf)
            #pragma unroll
            for (int c = 0; c < 4; ++c) {
                int oc = nwarp * 64 + nf * 8 + (lane & 3) * 2 + (c & 1);
                int m  = mwarp * 32 + mf * 16 + (lane >> 2) + (c & 2) * 4;
                so[oc * 136 + m] = acc[mf][nf][c] + bias_s[oc];
            }
    __syncthreads();

    const int m_ = tid & 127;
    const int h  = tr * TR + (m_ >> 4);
    const int w_ = tc * TC + (m_ & 15);
    const int oc_half = tid >> 7;   // 0 or 1
    float* ob = out + ((size_t)b * C_OUT) * HH * WW + (size_t)h * WW + w_;
    #pragma unroll 8
    for (int j = 0; j < 64; ++j) {
        int oc = j * 2 + oc_half;
        ob[(size_t)oc * HH * WW] = so[oc * 136 + m_];
    }
}

// ---------------- launch ----------------
extern "C" void kernel_launch(void* const* d_in, const int* in_sizes, int n_in,
                              void* d_out, int out_size) {
    const float* x    = (const float*)d_in[0];
    const float* wgt  = (const float*)d_in[1];
    const float* bias = (const float*)d_in[2];
    float* out = (float*)d_out;

    prep_weights<<<(NTAP * C_OUT * C_IN + 255) / 256, 256>>>(wgt);
    cudaFuncSetAttribute(oct_mma_kernel, cudaFuncAttributeMaxDynamicSharedMemorySize, SMEM_MAIN);
    {
        dim3 g(128, BATCH);   // 16x8 tiles of 8x16 pixels, per batch
        oct_mma_kernel<<<g, 256, SMEM_MAIN>>>(x, bias, out);
    }
}

// round 7
// speedup vs baseline: 1.1406x; 1.1406x over previous
#include <cuda_runtime.h>
#include <cuda_fp16.h>
#include <cstdint>

// ---------------- problem constants ----------------
#define BATCH   16
#define C_IN    64
#define C_OUT   128
#define HH      128
#define WW      128
#define PW      130              // padded width/height
#define PIX_PAD (PW*PW)          // 16900 padded pixels
#define XT_ROWS 16904
#define NTAP    9

// ---- output tile: 2 rows x 64 cols = 128 pixels (M) ----
#define TR      2
#define TC      64
#define AH      4                // window rows  (TR + 2)
#define AW      66               // window cols  (TC + 2)
#define A_ROWS  (AH * AW)        // 264 pixel-rows

// ---- smem layout (dynamic) ----
#define ROWB     144
#define A_BYTES  (A_ROWS * ROWB)            // 38016
#define B_TILE   (128 * ROWB)               // 18432
#define NSTAGE   3
#define SMEM_B0  A_BYTES
#define SMEM_MAIN (A_BYTES + NSTAGE * B_TILE)   // 93312

// ---------------- device globals (scratch) ----------------
__device__ __half g_xt[(size_t)BATCH * XT_ROWS * C_IN];   // [b][pixel][ic]
__device__ __half g_wt[NTAP * C_OUT * C_IN];              // [tap][oc][ic]

// ---------------- ptx helpers ----------------
__device__ __forceinline__ uint32_t smem_u32(const void* p) {
    uint32_t a;
    asm("{ .reg .u64 t; cvta.to.shared.u64 t, %1; cvt.u32.u64 %0, t; }" : "=r"(a) : "l"(p));
    return a;
}
__device__ __forceinline__ void cp_async16(uint32_t dst, const void* src) {
    asm volatile("cp.async.cg.shared.global [%0], [%1], 16;" :: "r"(dst), "l"(src));
}
__device__ __forceinline__ void cp_commit() {
    asm volatile("cp.async.commit_group;" ::: "memory");
}
template <int N>
__device__ __forceinline__ void cp_wait() {
    asm volatile("cp.async.wait_group %0;" :: "n"(N) : "memory");
}
__device__ __forceinline__ void ldm_x4(uint32_t& r0, uint32_t& r1, uint32_t& r2, uint32_t& r3, uint32_t addr) {
    asm volatile("ldmatrix.sync.aligned.m8n8.x4.shared.b16 {%0,%1,%2,%3}, [%4];"
                 : "=r"(r0), "=r"(r1), "=r"(r2), "=r"(r3) : "r"(addr));
}
__device__ __forceinline__ void mma16816(float* c, uint32_t a0, uint32_t a1, uint32_t a2, uint32_t a3,
                                         uint32_t b0, uint32_t b1) {
    asm volatile("mma.sync.aligned.m16n8k16.row.col.f32.f16.f16.f32 "
                 "{%0,%1,%2,%3}, {%4,%5,%6,%7}, {%8,%9}, {%0,%1,%2,%3};"
                 : "+f"(c[0]), "+f"(c[1]), "+f"(c[2]), "+f"(c[3])
                 : "r"(a0), "r"(a1), "r"(a2), "r"(a3), "r"(b0), "r"(b1));
}

// ---------------- fused prep: weights + x transform (R5 proven) ----------------
__global__ __launch_bounds__(256)
void prep_fused(const float* __restrict__ x, const float* __restrict__ w) {
    __shared__ float buf[64][133];
    const int tid = threadIdx.x;

    if (blockIdx.y == BATCH) {
        for (int idx = blockIdx.x * 256 + tid; idx < NTAP * C_OUT * C_IN; idx += PW * 256) {
            int ic  = idx & 63;
            int oc  = (idx >> 6) & 127;
            int tap = idx >> 13;
            int i = oc >> 3, p = oc & 7;
            int j = ic >> 3, q = ic & 7;
            int kh = tap / 3, kw = tap % 3;
            g_wt[idx] = __float2half_rn(w[i * 4608 + j * 576 + p * 72 + q * 9 + kh * 3 + kw]);
        }
        return;
    }

    const int hp = blockIdx.x;   // 0..129
    const int b  = blockIdx.y;
    __half* dst = g_xt + ((size_t)b * XT_ROWS + (size_t)hp * PW) * C_IN;

    if (hp == 0 || hp == PW - 1) {
        uint4 z = make_uint4(0, 0, 0, 0);
        for (int idx = tid; idx < PW * C_IN / 8; idx += 256) ((uint4*)dst)[idx] = z;
        if (hp == PW - 1) {
            uint4* g = (uint4*)(g_xt + ((size_t)b * XT_ROWS + PIX_PAD) * C_IN);
            for (int idx = tid; idx < 4 * C_IN / 8; idx += 256) g[idx] = z;
        }
        return;
    }
    const float* src = x + ((size_t)b * C_IN * HH + (size_t)(hp - 1)) * WW;
    for (int idx = tid; idx < C_IN * 32; idx += 256) {
        int ic = idx >> 5, f4 = idx & 31;
        float4 v = *(const float4*)(src + (size_t)ic * HH * WW + f4 * 4);
        buf[ic][1 + f4 * 4 + 0] = v.x;
        buf[ic][1 + f4 * 4 + 1] = v.y;
        buf[ic][1 + f4 * 4 + 2] = v.z;
        buf[ic][1 + f4 * 4 + 3] = v.w;
    }
    __syncthreads();
    __half2* d2 = (__half2*)dst;
    for (int idx = tid; idx < PW * 32; idx += 256) {
        int wp = idx >> 5, icp = idx & 31;
        float v0 = 0.0f, v1 = 0.0f;
        if (wp != 0 && wp != PW - 1) {
            v0 = buf[icp * 2 + 0][wp];
            v1 = buf[icp * 2 + 1][wp];
        }
        d2[(size_t)wp * 32 + icp] = __floats2half2_rn(v0, v1);
    }
}

// ---------------- B-tap loader (cp.async, one commit group) ----------------
__device__ __forceinline__ void load_B(uint32_t sB, int tap, int tid) {
    const __half* bsrc = g_wt + (size_t)tap * C_OUT * C_IN;
    #pragma unroll
    for (int i = 0; i < 4; ++i) {
        int idx = tid + i * 256;
        int oc = idx >> 3, c = idx & 7;
        cp_async16(sB + oc * ROWB + c * 16, bsrc + (size_t)oc * C_IN + c * 8);
    }
    cp_commit();
}

// ---------------- main kernel ----------------
__global__ __launch_bounds__(256, 2)
void oct_mma_kernel(const float* __restrict__ bias, float* __restrict__ out) {
    extern __shared__ char smem[];
    __shared__ float bias_s[C_OUT];
    const uint32_t sb = smem_u32(smem);
    const int tid  = threadIdx.x;
    const int wid  = tid >> 5;
    const int lane = tid & 31;
    const int mwarp = wid & 3;        // m block of 32
    const int nwarp = wid >> 2;       // n block of 64

    const int tc = blockIdx.x & 1;    // tile col (64 px)
    const int tr = blockIdx.x >> 1;   // tile row (2 px), 0..63
    const int b  = blockIdx.y;        // batch

    const int R0 = tr * TR;           // window origin in padded coords
    const int C0 = tc * TC;

    if (tid < C_OUT) bias_s[tid] = bias[tid];

    // ---- group 0: A window rows (once): 264 rows x 128B from g_xt ----
    {
        const __half* xtb = g_xt + ((size_t)b * XT_ROWS) * C_IN;
        for (int idx = tid; idx < A_ROWS * 8; idx += 256) {
            int m = idx >> 3, c = idx & 7;
            int r = m / AW, col = m - r * AW;
            const __half* src = xtb + ((size_t)(R0 + r) * PW + (C0 + col)) * C_IN + c * 8;
            cp_async16(sb + m * ROWB + c * 16, src);
        }
        cp_commit();
    }
    // ---- groups 1,2: B taps 0,1 ----
    load_B(sb + SMEM_B0 + 0 * B_TILE, 0, tid);
    load_B(sb + SMEM_B0 + 1 * B_TILE, 1, tid);

    float acc[2][8][4];
    #pragma unroll
    for (int mf = 0; mf < 2; ++mf)
        #pragma unroll
        for (int nf = 0; nf < 8; ++nf)
            #pragma unroll
            for (int c = 0; c < 4; ++c) acc[mf][nf][c] = 0.0f;

    // lane-constant ldmatrix offsets
    // fragment f = 2*mwarp + mf: window row rr = f>>2, col0 = (f&3)*16
    const int a_row_local = ((lane >> 3) & 1) * 8 + (lane & 7);    // 0..15 pixel within fragment
    const int rr0 = mwarp >> 1;
    const int c00 = (mwarp & 1) * 32;
    const uint32_t a_off = (uint32_t)(rr0 * AW + c00 + a_row_local) * ROWB + (lane >> 4) * 16;
    const int b_row = ((lane >> 4) << 3) + (lane & 7);
    const uint32_t b_off = (uint32_t)(nwarp * 64 + b_row) * ROWB + ((lane >> 3) & 1) * 16;

    const int shifts[NTAP] = {0, 1, 2, AW, AW + 1, AW + 2, 2 * AW, 2 * AW + 1, 2 * AW + 2};

    #pragma unroll
    for (int t = 0; t < NTAP; ++t) {
        if (t < NTAP - 1) cp_wait<1>(); else cp_wait<0>();
        __syncthreads();
        if (t + 2 < NTAP)
            load_B(sb + SMEM_B0 + (uint32_t)((t + 2) % NSTAGE) * B_TILE, t + 2, tid);

        const uint32_t aB = sb + a_off + (uint32_t)shifts[t] * ROWB;
        const uint32_t bB = sb + SMEM_B0 + (uint32_t)(t % NSTAGE) * B_TILE + b_off;
        #pragma unroll
        for (int ks = 0; ks < 4; ++ks) {
            uint32_t a0[4], a1[4];
            ldm_x4(a0[0], a0[1], a0[2], a0[3], aB + ks * 32);
            ldm_x4(a1[0], a1[1], a1[2], a1[3], aB + 16 * ROWB + ks * 32);   // mf=1: +16 cols
            #pragma unroll
            for (int nf2 = 0; nf2 < 4; ++nf2) {
                uint32_t bb[4];
                ldm_x4(bb[0], bb[1], bb[2], bb[3], bB + nf2 * 16 * ROWB + ks * 32);
                mma16816(acc[0][nf2 * 2 + 0], a0[0], a0[1], a0[2], a0[3], bb[0], bb[1]);
                mma16816(acc[0][nf2 * 2 + 1], a0[0], a0[1], a0[2], a0[3], bb[2], bb[3]);
                mma16816(acc[1][nf2 * 2 + 0], a1[0], a1[1], a1[2], a1[3], bb[0], bb[1]);
                mma16816(acc[1][nf2 * 2 + 1], a1[0], a1[1], a1[2], a1[3], bb[2], bb[3]);
            }
        }
    }
    __syncthreads();   // protect smem reuse by epilogue

    // ---- epilogue: transpose (bias folded) through smem -> coalesced stores ----
    float* so = (float*)smem;   // [oc][136]
    #pragma unroll
    for (int mf = 0; mf < 2; ++mf)
        #pragma unroll
        for (int nf = 0; nf < 8; ++nf)
            #pragma unroll
            for (int c = 0; c < 4; ++c) {
                int oc = nwarp * 64 + nf * 8 + (lane & 3) * 2 + (c & 1);
                int m  = mwarp * 32 + mf * 16 + (lane >> 2) + (c & 2) * 4;
                so[oc * 136 + m] = acc[mf][nf][c] + bias_s[oc];
            }
    __syncthreads();

    const int m_ = tid & 127;
    const int h  = R0 + (m_ >> 6);        // m = rr*64 + cc
    const int w_ = C0 + (m_ & 63);
    const int oc_half = tid >> 7;   // 0 or 1
    float* ob = out + ((size_t)b * C_OUT) * HH * WW + (size_t)h * WW + w_;
    #pragma unroll 8
    for (int j = 0; j < 64; ++j) {
        int oc = j * 2 + oc_half;
        ob[(size_t)oc * HH * WW] = so[oc * 136 + m_];
    }
}

// ---------------- launch ----------------
extern "C" void kernel_launch(void* const* d_in, const int* in_sizes, int n_in,
                              void* d_out, int out_size) {
    const float* x    = (const float*)d_in[0];
    const float* wgt  = (const float*)d_in[1];
    const float* bias = (const float*)d_in[2];
    float* out = (float*)d_out;

    {
        dim3 g(PW, BATCH + 1);          // y==BATCH rows do weight repack
        prep_fused<<<g, 256>>>(x, wgt);
    }
    cudaFuncSetAttribute(oct_mma_kernel, cudaFuncAttributeMaxDynamicSharedMemorySize, SMEM_MAIN);
    {
        dim3 g((HH / TR) * (WW / TC), BATCH);   // 64x2 tiles = 128, x16 batches
        oct_mma_kernel<<<g, 256, SMEM_MAIN>>>(bias, out);
    }
}

// round 8
// speedup vs baseline: 1.2027x; 1.0545x over previous
#include <cuda_runtime.h>
#include <cuda_fp16.h>
#include <cstdint>

// ---------------- problem constants ----------------
#define BATCH   16
#define C_IN    64
#define C_OUT   128
#define HH      128
#define WW      128
#define PW      130              // padded width/height
#define PIX_PAD (PW*PW)
#define XT_ROWS 16904
#define NTAP    9

// ---- output tile: 2 rows x 64 cols = 128 pixels (M) ----
#define TR      2
#define TC      64
#define AH      4                // window rows  (TR + 2)
#define AW      66               // window cols  (TC + 2)
#define A_ROWS  (AH * AW)        // 264 pixel-rows

// ---- smem layout (dynamic) ----
#define ROWB     144
#define A_BYTES  (A_ROWS * ROWB)            // 38016
#define B_TILE   (128 * ROWB)               // 18432
#define NSTAGE   3
#define SMEM_B0  A_BYTES
#define SMEM_MAIN (A_BYTES + NSTAGE * B_TILE)   // 93312

#define NTHREADS 128

// ---------------- device globals (scratch) ----------------
__device__ __half g_xt[(size_t)BATCH * XT_ROWS * C_IN];   // [b][pixel][ic]
__device__ __half g_wt[NTAP * C_OUT * C_IN];              // [tap][oc][ic]

// ---------------- ptx helpers ----------------
__device__ __forceinline__ uint32_t smem_u32(const void* p) {
    uint32_t a;
    asm("{ .reg .u64 t; cvta.to.shared.u64 t, %1; cvt.u32.u64 %0, t; }" : "=r"(a) : "l"(p));
    return a;
}
__device__ __forceinline__ void cp_async16(uint32_t dst, const void* src) {
    asm volatile("cp.async.cg.shared.global [%0], [%1], 16;" :: "r"(dst), "l"(src));
}
__device__ __forceinline__ void cp_commit() {
    asm volatile("cp.async.commit_group;" ::: "memory");
}
template <int N>
__device__ __forceinline__ void cp_wait() {
    asm volatile("cp.async.wait_group %0;" :: "n"(N) : "memory");
}
__device__ __forceinline__ void ldm_x4(uint32_t& r0, uint32_t& r1, uint32_t& r2, uint32_t& r3, uint32_t addr) {
    asm volatile("ldmatrix.sync.aligned.m8n8.x4.shared.b16 {%0,%1,%2,%3}, [%4];"
                 : "=r"(r0), "=r"(r1), "=r"(r2), "=r"(r3) : "r"(addr));
}
__device__ __forceinline__ void mma16816(float* c, const uint32_t* a, uint32_t b0, uint32_t b1) {
    asm volatile("mma.sync.aligned.m16n8k16.row.col.f32.f16.f16.f32 "
                 "{%0,%1,%2,%3}, {%4,%5,%6,%7}, {%8,%9}, {%0,%1,%2,%3};"
                 : "+f"(c[0]), "+f"(c[1]), "+f"(c[2]), "+f"(c[3])
                 : "r"(a[0]), "r"(a[1]), "r"(a[2]), "r"(a[3]), "r"(b0), "r"(b1));
}

// ---------------- fused prep: weights + x transform (proven) ----------------
__global__ __launch_bounds__(256)
void prep_fused(const float* __restrict__ x, const float* __restrict__ w) {
    __shared__ float buf[64][133];
    const int tid = threadIdx.x;

    if (blockIdx.y == BATCH) {
        for (int idx = blockIdx.x * 256 + tid; idx < NTAP * C_OUT * C_IN; idx += PW * 256) {
            int ic  = idx & 63;
            int oc  = (idx >> 6) & 127;
            int tap = idx >> 13;
            int i = oc >> 3, p = oc & 7;
            int j = ic >> 3, q = ic & 7;
            int kh = tap / 3, kw = tap % 3;
            g_wt[idx] = __float2half_rn(w[i * 4608 + j * 576 + p * 72 + q * 9 + kh * 3 + kw]);
        }
        return;
    }

    const int hp = blockIdx.x;   // 0..129
    const int b  = blockIdx.y;
    __half* dst = g_xt + ((size_t)b * XT_ROWS + (size_t)hp * PW) * C_IN;

    if (hp == 0 || hp == PW - 1) {
        uint4 z = make_uint4(0, 0, 0, 0);
        for (int idx = tid; idx < PW * C_IN / 8; idx += 256) ((uint4*)dst)[idx] = z;
        if (hp == PW - 1) {
            uint4* g = (uint4*)(g_xt + ((size_t)b * XT_ROWS + PIX_PAD) * C_IN);
            for (int idx = tid; idx < 4 * C_IN / 8; idx += 256) g[idx] = z;
        }
        return;
    }
    const float* src = x + ((size_t)b * C_IN * HH + (size_t)(hp - 1)) * WW;
    for (int idx = tid; idx < C_IN * 32; idx += 256) {
        int ic = idx >> 5, f4 = idx & 31;
        float4 v = *(const float4*)(src + (size_t)ic * HH * WW + f4 * 4);
        buf[ic][1 + f4 * 4 + 0] = v.x;
        buf[ic][1 + f4 * 4 + 1] = v.y;
        buf[ic][1 + f4 * 4 + 2] = v.z;
        buf[ic][1 + f4 * 4 + 3] = v.w;
    }
    __syncthreads();
    __half2* d2 = (__half2*)dst;
    for (int idx = tid; idx < PW * 32; idx += 256) {
        int wp = idx >> 5, icp = idx & 31;
        float v0 = 0.0f, v1 = 0.0f;
        if (wp != 0 && wp != PW - 1) {
            v0 = buf[icp * 2 + 0][wp];
            v1 = buf[icp * 2 + 1][wp];
        }
        d2[(size_t)wp * 32 + icp] = __floats2half2_rn(v0, v1);
    }
}

// ---------------- B-tap loader (cp.async, one commit group) ----------------
__device__ __forceinline__ void load_B(uint32_t sB, int tap, int tid) {
    const __half* bsrc = g_wt + (size_t)tap * C_OUT * C_IN;
    #pragma unroll
    for (int i = 0; i < 8; ++i) {
        int idx = tid + i * NTHREADS;
        int oc = idx >> 3, c = idx & 7;
        cp_async16(sB + oc * ROWB + c * 16, bsrc + (size_t)oc * C_IN + c * 8);
    }
    cp_commit();
}

// ---------------- main kernel: 4 warps, 64x64 warp tiles ----------------
__global__ __launch_bounds__(NTHREADS, 2)
void oct_mma_kernel(const float* __restrict__ bias, float* __restrict__ out) {
    extern __shared__ char smem[];
    __shared__ float bias_s[C_OUT];
    const uint32_t sb = smem_u32(smem);
    const int tid  = threadIdx.x;
    const int wid  = tid >> 5;
    const int lane = tid & 31;
    const int mwarp = wid & 1;        // m half: output row 0 or 1 (64 px each)
    const int nwarp = wid >> 1;       // n half: oc 0-63 or 64-127

    const int tc = blockIdx.x & 1;    // tile col (64 px)
    const int tr = blockIdx.x >> 1;   // tile row (2 px), 0..63
    const int b  = blockIdx.y;        // batch

    const int R0 = tr * TR;
    const int C0 = tc * TC;

    bias_s[tid] = bias[tid];

    // ---- group 0: A window rows (once): 264 rows x 128B from g_xt ----
    {
        const __half* xtb = g_xt + ((size_t)b * XT_ROWS) * C_IN;
        for (int idx = tid; idx < A_ROWS * 8; idx += NTHREADS) {
            int m = idx >> 3, c = idx & 7;
            int r = m / AW, col = m - r * AW;
            const __half* src = xtb + ((size_t)(R0 + r) * PW + (C0 + col)) * C_IN + c * 8;
            cp_async16(sb + m * ROWB + c * 16, src);
        }
        cp_commit();
    }
    // ---- groups 1,2: B taps 0,1 ----
    load_B(sb + SMEM_B0 + 0 * B_TILE, 0, tid);
    load_B(sb + SMEM_B0 + 1 * B_TILE, 1, tid);

    float acc[4][8][4];
    #pragma unroll
    for (int mf = 0; mf < 4; ++mf)
        #pragma unroll
        for (int nf = 0; nf < 8; ++nf)
            #pragma unroll
            for (int c = 0; c < 4; ++c) acc[mf][nf][c] = 0.0f;

    // lane-constant ldmatrix offsets
    // A: warp covers window row 'mwarp', cols mf*16..mf*16+15 (+halo shift per tap)
    const int a_row_local = ((lane >> 3) & 1) * 8 + (lane & 7);
    const uint32_t a_off = (uint32_t)(mwarp * AW + a_row_local) * ROWB + (lane >> 4) * 16;
    const int b_row = ((lane >> 4) << 3) + (lane & 7);
    const uint32_t b_off = (uint32_t)(nwarp * 64 + b_row) * ROWB + ((lane >> 3) & 1) * 16;

    const int shifts[NTAP] = {0, 1, 2, AW, AW + 1, AW + 2, 2 * AW, 2 * AW + 1, 2 * AW + 2};

    #pragma unroll
    for (int t = 0; t < NTAP; ++t) {
        if (t < NTAP - 1) cp_wait<1>(); else cp_wait<0>();
        __syncthreads();
        if (t + 2 < NTAP)
            load_B(sb + SMEM_B0 + (uint32_t)((t + 2) % NSTAGE) * B_TILE, t + 2, tid);

        const uint32_t aB = sb + a_off + (uint32_t)shifts[t] * ROWB;
        const uint32_t bB = sb + SMEM_B0 + (uint32_t)(t % NSTAGE) * B_TILE + b_off;
        #pragma unroll
        for (int ks = 0; ks < 4; ++ks) {
            uint32_t a[4][4];
            #pragma unroll
            for (int mf = 0; mf < 4; ++mf)
                ldm_x4(a[mf][0], a[mf][1], a[mf][2], a[mf][3], aB + mf * 16 * ROWB + ks * 32);
            #pragma unroll
            for (int nf2 = 0; nf2 < 4; ++nf2) {
                uint32_t bb[4];
                ldm_x4(bb[0], bb[1], bb[2], bb[3], bB + nf2 * 16 * ROWB + ks * 32);
                #pragma unroll
                for (int mf = 0; mf < 4; ++mf) {
                    mma16816(acc[mf][nf2 * 2 + 0], a[mf], bb[0], bb[1]);
                    mma16816(acc[mf][nf2 * 2 + 1], a[mf], bb[2], bb[3]);
                }
            }
        }
    }
    __syncthreads();   // protect smem reuse by epilogue

    // ---- epilogue: transpose (bias folded) through smem -> coalesced stores ----
    float* so = (float*)smem;   // [oc][136]
    #pragma unroll
    for (int mf = 0; mf < 4; ++mf)
        #pragma unroll
        for (int nf = 0; nf < 8; ++nf)
            #pragma unroll
            for (int c = 0; c < 4; ++c) {
                int oc = nwarp * 64 + nf * 8 + (lane & 3) * 2 + (c & 1);
                int m  = mwarp * 64 + mf * 16 + (lane >> 2) + (c & 2) * 4;
                so[oc * 136 + m] = acc[mf][nf][c] + bias_s[oc];
            }
    __syncthreads();

    const int m_ = tid;                  // 0..127 : pixel index
    const int h  = R0 + (m_ >> 6);
    const int w_ = C0 + (m_ & 63);
    float* ob = out + ((size_t)b * C_OUT) * HH * WW + (size_t)h * WW + w_;
    #pragma unroll 8
    for (int oc = 0; oc < C_OUT; ++oc)
        ob[(size_t)oc * HH * WW] = so[oc * 136 + m_];
}

// ---------------- launch ----------------
extern "C" void kernel_launch(void* const* d_in, const int* in_sizes, int n_in,
                              void* d_out, int out_size) {
    const float* x    = (const float*)d_in[0];
    const float* wgt  = (const float*)d_in[1];
    const float* bias = (const float*)d_in[2];
    float* out = (float*)d_out;

    {
        dim3 g(PW, BATCH + 1);          // y==BATCH rows do weight repack
        prep_fused<<<g, 256>>>(x, wgt);
    }
    cudaFuncSetAttribute(oct_mma_kernel, cudaFuncAttributeMaxDynamicSharedMemorySize, SMEM_MAIN);
    {
        dim3 g((HH / TR) * (WW / TC), BATCH);   // 128 tiles x 16 batches
        oct_mma_kernel<<<g, NTHREADS, SMEM_MAIN>>>(bias, out);
    }
}